// round 14
// baseline (speedup 1.0000x reference)
#include <cuda_runtime.h>
#include <cuda_fp16.h>
#include <cstdint>

#define Nn   20000
#define Ee   320000
#define XDIM 128
#define Hh   256
#define LL   4
#define GG   128
#define CC   10
#define EPSF 1e-5f

// weight kp layout: [0,64) fused We@W0 (K=128); [64+128*(l-1), ...) conv layer l=1..3 (K=256)
#define KP2TOT (64 + 3 * 128)            // 448 packed k-pair rows

// ---------------- scratch ----------------
__device__ float g_t [Nn * Hh];          // GEMM output (pre-agg)
__device__ float g_t2[Nn * Hh];          // post-agg (pre-BN; A for next layer)
__device__ float g_w0f[XDIM * Hh];       // fused We@W0 (fp32)
__device__ float g_bias0[Hh];            // encB@W0
__device__ unsigned int g_wbh[KP2TOT * Hh];
__device__ unsigned int g_wbl[KP2TOT * Hh];
__device__ float g_dinv[Nn];
__device__ int   g_deg[Nn];
__device__ int   g_rowptr[Nn + 1];
__device__ int   g_cursor[Nn];
__device__ int   g_csrc[Ee];
__device__ float g_cw[Ee];
__device__ float g_colsum[Hh];
__device__ float g_colsq[Hh];
__device__ float g_scale[Hh];
__device__ float g_shift[Hh];
__device__ int   g_ctr;
__device__ float g_gsum[GG * Hh];
__device__ int   g_gcnt[GG];
__device__ float g_m1[GG * Hh];
__device__ float g_m2[GG * Hh];

// ---------------- fp16 split helpers ----------------
__device__ __forceinline__ void split_h2(float a, float b,
                                         unsigned int& hi, unsigned int& lo) {
    __half ha = __float2half_rn(a), hb = __float2half_rn(b);
    float ra = a - __half2float(ha);
    float rb = b - __half2float(hb);
    __half2 h = __halves2half2(ha, hb);
    __half2 l = __halves2half2(__float2half_rn(ra), __float2half_rn(rb));
    hi = *reinterpret_cast<unsigned int*>(&h);
    lo = *reinterpret_cast<unsigned int*>(&l);
}

__device__ __forceinline__ void mma_f16(float4& d,
    unsigned int a0, unsigned int a1, unsigned int a2, unsigned int a3,
    unsigned int b0, unsigned int b1)
{
    asm volatile(
        "mma.sync.aligned.m16n8k16.row.col.f32.f16.f16.f32 "
        "{%0,%1,%2,%3}, {%4,%5,%6,%7}, {%8,%9}, {%0,%1,%2,%3};\n"
        : "+f"(d.x), "+f"(d.y), "+f"(d.z), "+f"(d.w)
        : "r"(a0), "r"(a1), "r"(a2), "r"(a3), "r"(b0), "r"(b1));
}

// ---------------- setup ----------------
__global__ void zero_k() {
    int i = blockIdx.x * blockDim.x + threadIdx.x;
    if (i < Nn)      g_deg[i]  = 0;
    if (i < GG * Hh) g_gsum[i] = 0.f;
    if (i < GG)      g_gcnt[i] = 0;
    if (i < Hh)      { g_colsum[i] = 0.f; g_colsq[i] = 0.f; }
    if (i == 0)      g_ctr = 0;
}

// fused weight GEMM: g_w0f = We @ W0 ; g_bias0 = encB @ W0
__global__ void wprep_k(const float* __restrict__ encW, const float* __restrict__ encB,
                        const float* __restrict__ convW0) {
    __shared__ float row[Hh];
    int k = blockIdx.x;
    int n = threadIdx.x;
    const float* src = (k < XDIM) ? (encW + (size_t)k * Hh) : encB;
    row[n] = src[n];
    __syncthreads();
    float sum = 0.f;
#pragma unroll 8
    for (int j = 0; j < Hh; j++) sum += row[j] * convW0[(size_t)j * Hh + n];
    if (k < XDIM) g_w0f[(size_t)k * Hh + n] = sum;
    else          g_bias0[n] = sum;
}

// pre-split + pre-pack weights into fp16 hi/lo, k-pair packed layout [kp][256]
__global__ void prep_k(const float* __restrict__ convW) {
    int i = blockIdx.x * blockDim.x + threadIdx.x;
    if (i >= KP2TOT * Hh) return;
    int kp = i >> 8;
    int n  = i & 255;
    int r0 = kp * 2, r1 = r0 + 1;
    float a, b;
    if (kp < 64) {
        a = g_w0f[(size_t)r0 * Hh + n];
        b = g_w0f[(size_t)r1 * Hh + n];
    } else {
        a = convW[(size_t)(r0 + 128) * Hh + n];
        b = convW[(size_t)(r1 + 128) * Hh + n];
    }
    unsigned int hi, lo;
    split_h2(a, b, hi, lo);
    g_wbh[i] = hi;
    g_wbl[i] = lo;
}

__global__ void degree_k(const int* __restrict__ dst, const int* __restrict__ batch) {
    int i = blockIdx.x * blockDim.x + threadIdx.x;
    if (i < Ee) atomicAdd(&g_deg[dst[i]], 1);
    if (i < Nn) atomicAdd(&g_gcnt[batch[i]], 1);
}

// scan (vectorized) + dinv
__global__ void scan_k() {
    __shared__ int wsum[32];
    const int CH = 20;
    int tid = threadIdx.x, lane = tid & 31, wid = tid >> 5;
    int base = tid * CH;
    int dv[CH];
    int s = 0;
    if (base < Nn) {
        const int4* dp = (const int4*)(g_deg + base);
#pragma unroll
        for (int q = 0; q < 5; q++) {
            int4 t = dp[q];
            dv[q * 4 + 0] = t.x; dv[q * 4 + 1] = t.y;
            dv[q * 4 + 2] = t.z; dv[q * 4 + 3] = t.w;
        }
#pragma unroll
        for (int c = 0; c < CH; c++) s += dv[c];
    }
    int inc = s;
#pragma unroll
    for (int o = 1; o < 32; o <<= 1) {
        int t = __shfl_up_sync(0xffffffffu, inc, o);
        if (lane >= o) inc += t;
    }
    if (lane == 31) wsum[wid] = inc;
    __syncthreads();
    if (wid == 0) {
        int v = wsum[lane];
        int iv = v;
#pragma unroll
        for (int o = 1; o < 32; o <<= 1) {
            int t = __shfl_up_sync(0xffffffffu, iv, o);
            if (lane >= o) iv += t;
        }
        wsum[lane] = iv - v;
    }
    __syncthreads();
    int off = wsum[wid] + (inc - s);
    if (base < Nn) {
        int p[CH];
        int run = off;
#pragma unroll
        for (int c = 0; c < CH; c++) { p[c] = run; run += dv[c]; }
        int4*   rp = (int4*)(g_rowptr + base);
        int4*   cp = (int4*)(g_cursor + base);
        float4* fp = (float4*)(g_dinv + base);
#pragma unroll
        for (int q = 0; q < 5; q++) {
            int4 t; t.x = p[q*4]; t.y = p[q*4+1]; t.z = p[q*4+2]; t.w = p[q*4+3];
            rp[q] = t; cp[q] = t;
            float4 f;
            f.x = rsqrtf((float)dv[q*4+0] + 1.f);
            f.y = rsqrtf((float)dv[q*4+1] + 1.f);
            f.z = rsqrtf((float)dv[q*4+2] + 1.f);
            f.w = rsqrtf((float)dv[q*4+3] + 1.f);
            fp[q] = f;
        }
    }
    if (base == Nn) g_rowptr[Nn] = off;
}

__global__ void place_k(const int* __restrict__ src, const int* __restrict__ dst) {
    int i = blockIdx.x * blockDim.x + threadIdx.x;
    if (i >= Ee) return;
    int s = src[i], d = dst[i];
    int pos = atomicAdd(&g_cursor[d], 1);
    g_csrc[pos] = s;
    g_cw[pos]   = g_dinv[s] * g_dinv[d];
}

// ---------------- split-FP16 tensor-core GEMM, BM=128 x BN=128, double-buffered ----------------
#define BM 128
#define BN 128
#define BK 16
// mode 0: fused first GEMM (A=x, K=128, +g_bias0,  -> g_t)
// mode 2: conv layers 1-3 (A=relu(g_t2*sc+sh), K=256, -> g_t)
__global__ __launch_bounds__(256) void gemm_k(const float* __restrict__ xin,
                                              int mode, int wofs2) {
    __shared__ unsigned int Ah[2][8][BM], Al[2][8][BM];
    __shared__ unsigned int Bh[2][8][BN], Bl[2][8][BN];

    const int K  = (mode == 0) ? XDIM : Hh;
    const int KT = K / BK;
    const float* A = (mode == 0) ? xin : g_t2;

    const int tid  = threadIdx.x;
    const int lane = tid & 31, wid = tid >> 5;
    const int warp_m = wid & 1, warp_n = wid >> 1;    // 2 x 4 warps, warp tile 64x32
    const int rowBase = blockIdx.y * BM, colBase = blockIdx.x * BN;

    const int arow = tid >> 1;            // 0..127
    const int ak8  = (tid & 1) * 8;       // 0 or 8
    const int akp  = (tid & 1) * 4;       // kpair plane base
    const int bkp  = tid >> 5;            // 0..7 kpair plane
    const int bcol = (tid & 31) * 4;      // 0..124
    const int q = lane >> 2, t = lane & 3, tsw = t << 3;

    const int gr = rowBase + arow;
    const float* aptr = A + (size_t)gr * K + ak8;
    const unsigned int* bhp = g_wbh + wofs2 + (size_t)bkp * Hh + colBase + bcol;
    const unsigned int* blp = g_wbl + wofs2 + (size_t)bkp * Hh + colBase + bcol;
    const int bstep = 8 * Hh;
    const int bcs = bcol ^ ((bkp & 3) << 3);

    float4 acc[4][4];
#pragma unroll
    for (int i = 0; i < 4; i++)
#pragma unroll
        for (int j = 0; j < 4; j++) acc[i][j] = make_float4(0.f, 0.f, 0.f, 0.f);

    float va[8];
    uint4 rbh, rbl;

    // ---- prologue: fetch tile 0 ----
    {
        float4 v0 = make_float4(0.f,0.f,0.f,0.f), v1 = v0;
        if (gr < Nn) { v0 = *(const float4*)aptr; v1 = *(const float4*)(aptr + 4); }
        va[0]=v0.x; va[1]=v0.y; va[2]=v0.z; va[3]=v0.w;
        va[4]=v1.x; va[5]=v1.y; va[6]=v1.z; va[7]=v1.w;
        if (mode == 2) {
            int kk = ak8;
#pragma unroll
            for (int c = 0; c < 8; c++)
                va[c] = fmaxf(va[c] * g_scale[kk + c] + g_shift[kk + c], 0.f);
        }
        rbh = *(const uint4*)bhp;
        rbl = *(const uint4*)blp;
    }
#pragma unroll
    for (int c2 = 0; c2 < 4; c2++) {
        unsigned int hi, lo;
        split_h2(va[2*c2], va[2*c2+1], hi, lo);
        int col = arow ^ (c2 << 3);
        Ah[0][akp + c2][col] = hi;
        Al[0][akp + c2][col] = lo;
    }
    *(uint4*)&Bh[0][bkp][bcs] = rbh;
    *(uint4*)&Bl[0][bkp][bcs] = rbl;
    __syncthreads();

    for (int kt = 0; kt < KT; kt++) {
        const int cur = kt & 1;
        const bool more = (kt + 1 < KT);
        // ---- prefetch next tile (overlaps MMAs) ----
        if (more) {
            float4 v0 = make_float4(0.f,0.f,0.f,0.f), v1 = v0;
            if (gr < Nn) {
                const float* ap = aptr + (kt + 1) * BK;
                v0 = *(const float4*)ap; v1 = *(const float4*)(ap + 4);
            }
            va[0]=v0.x; va[1]=v0.y; va[2]=v0.z; va[3]=v0.w;
            va[4]=v1.x; va[5]=v1.y; va[6]=v1.z; va[7]=v1.w;
            if (mode == 2) {
                int kk = (kt + 1) * BK + ak8;
#pragma unroll
                for (int c = 0; c < 8; c++)
                    va[c] = fmaxf(va[c] * g_scale[kk + c] + g_shift[kk + c], 0.f);
            }
            rbh = *(const uint4*)(bhp + (size_t)(kt + 1) * bstep);
            rbl = *(const uint4*)(blp + (size_t)(kt + 1) * bstep);
        }
        // ---- compute on cur buffer ----
        unsigned int bh0[4], bh1[4], bl0[4], bl1[4];
#pragma unroll
        for (int j = 0; j < 4; j++) {
            int nb = (warp_n * 32 + j * 8 + q) ^ tsw;
            bh0[j] = Bh[cur][t][nb];     bh1[j] = Bh[cur][t + 4][nb];
            bl0[j] = Bl[cur][t][nb];     bl1[j] = Bl[cur][t + 4][nb];
        }
#pragma unroll
        for (int i = 0; i < 4; i++) {
            int r  = warp_m * 64 + i * 16 + q;
            int rs  = r ^ tsw;
            int rs8 = (r + 8) ^ tsw;
            unsigned int ah0 = Ah[cur][t][rs],     ah1 = Ah[cur][t][rs8];
            unsigned int ah2 = Ah[cur][t + 4][rs], ah3 = Ah[cur][t + 4][rs8];
            unsigned int al0 = Al[cur][t][rs],     al1 = Al[cur][t][rs8];
            unsigned int al2 = Al[cur][t + 4][rs], al3 = Al[cur][t + 4][rs8];
#pragma unroll
            for (int j = 0; j < 4; j++) {
                mma_f16(acc[i][j], ah0, ah1, ah2, ah3, bh0[j], bh1[j]);
                mma_f16(acc[i][j], ah0, ah1, ah2, ah3, bl0[j], bl1[j]);
                mma_f16(acc[i][j], al0, al1, al2, al3, bh0[j], bh1[j]);
            }
        }
        // ---- store prefetched tile into next buffer ----
        if (more) {
            const int nxt = cur ^ 1;
#pragma unroll
            for (int c2 = 0; c2 < 4; c2++) {
                unsigned int hi, lo;
                split_h2(va[2*c2], va[2*c2+1], hi, lo);
                int col = arow ^ (c2 << 3);
                Ah[nxt][akp + c2][col] = hi;
                Al[nxt][akp + c2][col] = lo;
            }
            *(uint4*)&Bh[nxt][bkp][bcs] = rbh;
            *(uint4*)&Bl[nxt][bkp][bcs] = rbl;
        }
        __syncthreads();
    }

    // ---- epilogue ----
#pragma unroll
    for (int i = 0; i < 4; i++) {
#pragma unroll
        for (int j = 0; j < 4; j++) {
            int r0 = rowBase + warp_m * 64 + i * 16 + q;
            int c  = colBase + warp_n * 32 + j * 8 + t * 2;
            float bx = 0.f, by = 0.f;
            if (mode == 0) { bx = g_bias0[c]; by = g_bias0[c + 1]; }
            if (r0 < Nn) {
                g_t[(size_t)r0 * Hh + c]     = acc[i][j].x + bx;
                g_t[(size_t)r0 * Hh + c + 1] = acc[i][j].y + by;
            }
            if (r0 + 8 < Nn) {
                g_t[(size_t)(r0 + 8) * Hh + c]     = acc[i][j].z + bx;
                g_t[(size_t)(r0 + 8) * Hh + c + 1] = acc[i][j].w + by;
            }
        }
    }
}

// ---------------- aggregate: 2 warps (64 threads) per node + fused BN stats + bnprep ----------------
__global__ __launch_bounds__(256) void agg_k(const float* __restrict__ convBi,
                                             const float* __restrict__ gamma,
                                             const float* __restrict__ beta) {
    __shared__ float s_sum[Hh], s_sq[Hh];
    __shared__ int s_last;
    int tid = threadIdx.x;
    int sub = tid & 63;                    // 0..63: col group (4 cols each)
    s_sum[tid] = 0.f; s_sq[tid] = 0.f;
    __syncthreads();

    int w = blockIdx.x * 4 + (tid >> 6);   // grid = 5000 -> exact
    int beg = g_rowptr[w], end = g_rowptr[w + 1];
    float4 a0 = make_float4(0.f, 0.f, 0.f, 0.f);
    const float4* T = (const float4*)g_t;
    for (int e = beg; e < end; e++) {
        int   s  = g_csrc[e];
        float wt = g_cw[e];
        float4 v = T[s * 64 + sub];
        a0.x += v.x * wt; a0.y += v.y * wt; a0.z += v.z * wt; a0.w += v.w * wt;
    }
    float sn = g_dinv[w]; sn *= sn;
    float4 t0 = T[w * 64 + sub];
    float4 b0 = ((const float4*)convBi)[sub];
    a0.x += t0.x * sn + b0.x; a0.y += t0.y * sn + b0.y;
    a0.z += t0.z * sn + b0.z; a0.w += t0.w * sn + b0.w;
    ((float4*)g_t2)[w * 64 + sub] = a0;

    int c0 = sub * 4;
    atomicAdd(&s_sum[c0+0], a0.x); atomicAdd(&s_sum[c0+1], a0.y);
    atomicAdd(&s_sum[c0+2], a0.z); atomicAdd(&s_sum[c0+3], a0.w);
    atomicAdd(&s_sq[c0+0], a0.x*a0.x); atomicAdd(&s_sq[c0+1], a0.y*a0.y);
    atomicAdd(&s_sq[c0+2], a0.z*a0.z); atomicAdd(&s_sq[c0+3], a0.w*a0.w);
    __syncthreads();
    atomicAdd(&g_colsum[tid], s_sum[tid]);
    atomicAdd(&g_colsq[tid],  s_sq[tid]);

    // ---- last block computes BN scale/shift (fused bnprep) ----
    __threadfence();
    if (tid == 0) {
        int old = atomicAdd(&g_ctr, 1);
        s_last = (old == gridDim.x - 1);
    }
    __syncthreads();
    if (s_last) {
        __threadfence();
        const float invN = 1.f / (float)Nn;
        float m  = g_colsum[tid] * invN;
        float v  = g_colsq[tid] * invN - m * m;
        float rs = rsqrtf(v + EPSF);
        float sc = gamma[tid] * rs;
        g_scale[tid] = sc;
        g_shift[tid] = beta[tid] - m * sc;
        g_colsum[tid] = 0.f;
        g_colsq[tid]  = 0.f;
        if (tid == 0) g_ctr = 0;
    }
}

// ---------------- global mean pool with fused final BN+ReLU ----------------
__global__ void pool_k(const int* __restrict__ batch) {
    int j  = threadIdx.x;
    float sc = g_scale[j], sh = g_shift[j];
    int r0 = blockIdx.x * 80;
    int cur = -1;
    float acc = 0.f;
    for (int r = 0; r < 80; r++) {
        int n = r0 + r;
        if (n >= Nn) break;
        int b = batch[n];
        if (b != cur) {
            if (cur >= 0) atomicAdd(&g_gsum[cur * Hh + j], acc);
            cur = b; acc = 0.f;
        }
        acc += fmaxf(g_t2[(size_t)n * Hh + j] * sc + sh, 0.f);
    }
    if (cur >= 0) atomicAdd(&g_gsum[cur * Hh + j], acc);
}

// ---------------- MLP head ----------------
__global__ void mlp1_k(const float* __restrict__ W, const float* __restrict__ b) {
    __shared__ float s[Hh];
    int tid = threadIdx.x;
    int g   = blockIdx.x;
    float inv = 1.f / fmaxf((float)g_gcnt[g], 1.f);
    s[tid] = g_gsum[g * Hh + tid] * inv;
    __syncthreads();
    float sum = b[tid];
#pragma unroll 8
    for (int k = 0; k < Hh; k++) sum += s[k] * W[k * Hh + tid];
    g_m1[g * Hh + tid] = sum;
}

__global__ void mlp2_k(const float* __restrict__ gamma, const float* __restrict__ beta,
                       const float* __restrict__ W, const float* __restrict__ b) {
    __shared__ float s[Hh];
    int tid = threadIdx.x;
    int g   = blockIdx.x;
    float su = 0.f, q = 0.f;
    for (int r = 0; r < GG; r++) { float v = g_m1[r * Hh + tid]; su += v; q += v * v; }
    float m   = su * (1.f / GG);
    float var = q * (1.f / GG) - m * m;
    float sc  = gamma[tid] * rsqrtf(var + EPSF);
    float sh  = beta[tid] - m * sc;
    s[tid] = fmaxf(g_m1[g * Hh + tid] * sc + sh, 0.f);
    __syncthreads();
    float sum = b[tid];
#pragma unroll 8
    for (int k = 0; k < Hh; k++) sum += s[k] * W[k * Hh + tid];
    g_m2[g * Hh + tid] = sum;
}

__global__ void final_k(const float* __restrict__ gamma, const float* __restrict__ beta,
                        const float* __restrict__ W3, const float* __restrict__ b3,
                        float* __restrict__ out) {
    __shared__ float s[Hh];
    int tid = threadIdx.x;
    int g   = blockIdx.x;
    float su = 0.f, q = 0.f;
    for (int r = 0; r < GG; r++) { float v = g_m2[r * Hh + tid]; su += v; q += v * v; }
    float m   = su * (1.f / GG);
    float var = q * (1.f / GG) - m * m;
    float sc  = gamma[tid] * rsqrtf(var + EPSF);
    float sh  = beta[tid] - m * sc;
    s[tid] = g_m2[g * Hh + tid] * sc + sh;
    __syncthreads();
    if (tid < CC) {
        float sum = b3[tid];
        for (int k = 0; k < Hh; k++) sum += s[k] * W3[k * CC + tid];
        out[g * CC + tid] = sum;
    }
}

// ---------------- launch ----------------
extern "C" void kernel_launch(void* const* d_in, const int* in_sizes, int n_in,
                              void* d_out, int out_size) {
    const float* x     = (const float*)d_in[0];
    const int*   ei    = (const int*)  d_in[1];
    const int*   batch = (const int*)  d_in[2];
    const float* encW  = (const float*)d_in[3];
    const float* encB  = (const float*)d_in[4];
    const float* convW = (const float*)d_in[5];
    const float* convB = (const float*)d_in[6];
    const float* bnG   = (const float*)d_in[7];
    const float* bnB   = (const float*)d_in[8];
    const float* fcW1  = (const float*)d_in[9];
    const float* fcB1  = (const float*)d_in[10];
    const float* fcG1  = (const float*)d_in[11];
    const float* fcBe1 = (const float*)d_in[12];
    const float* fcW2  = (const float*)d_in[13];
    const float* fcB2  = (const float*)d_in[14];
    const float* fcG2  = (const float*)d_in[15];
    const float* fcBe2 = (const float*)d_in[16];
    const float* fcW3  = (const float*)d_in[17];
    const float* fcB3  = (const float*)d_in[18];
    const int* srcp = ei;
    const int* dstp = ei + Ee;
    float* out = (float*)d_out;

    dim3 gg(Hh / BN, (Nn + BM - 1) / BM);   // (2, 157)

    zero_k <<<(GG * Hh + 255) / 256, 256>>>();
    wprep_k<<<XDIM + 1, 256>>>(encW, encB, convW);
    prep_k <<<(KP2TOT * Hh + 255) / 256, 256>>>(convW);
    gemm_k <<<gg, 256>>>(x, 0, 0);                 // fused enc+conv0 [capture]

    degree_k<<<(Ee + 255) / 256, 256>>>(dstp, batch);
    scan_k  <<<1, 1024>>>();
    place_k <<<(Ee + 255) / 256, 256>>>(srcp, dstp);

    agg_k<<<Nn / 4, 256>>>(convB, bnG, bnB);
    for (int l = 1; l < LL; l++) {
        gemm_k<<<gg, 256>>>(nullptr, 2, (64 + (l - 1) * 128) * Hh);
        agg_k <<<Nn / 4, 256>>>(convB + l * Hh, bnG + l * Hh, bnB + l * Hh);
    }

    pool_k <<<250, 256>>>(batch);
    mlp1_k <<<GG, 256>>>(fcW1, fcB1);
    mlp2_k <<<GG, 256>>>(fcG1, fcBe1, fcW2, fcB2);
    final_k<<<GG, 256>>>(fcG2, fcBe2, fcW3, fcB3, out);
}

// round 15
// speedup vs baseline: 1.0809x; 1.0809x over previous
#include <cuda_runtime.h>
#include <cuda_fp16.h>
#include <cstdint>

#define Nn   20000
#define Ee   320000
#define XDIM 128
#define Hh   256
#define LL   4
#define GG   128
#define CC   10
#define EPSF 1e-5f

// weight kp layout: [0,64) fused We@W0 (K=128); [64+128*(l-1), ...) conv layer l=1..3 (K=256)
#define KP2TOT (64 + 3 * 128)            // 448 packed k-pair rows

// ---------------- scratch ----------------
__device__ float g_t [Nn * Hh];          // GEMM output (pre-agg)
__device__ float g_t2[Nn * Hh];          // post-agg (pre-BN; A for next layer)
__device__ float g_bias0[Hh];            // encB@W0
__device__ unsigned int g_wbh[KP2TOT * Hh];
__device__ unsigned int g_wbl[KP2TOT * Hh];
__device__ float g_dinv[Nn];
__device__ int   g_deg[Nn];
__device__ int   g_rowptr[Nn + 1];
__device__ int   g_cursor[Nn];
__device__ int   g_csrc[Ee];
__device__ float g_cw[Ee];
__device__ float g_colsum[Hh];
__device__ float g_colsq[Hh];
__device__ float g_scale[Hh];
__device__ float g_shift[Hh];
__device__ int   g_ctr;
__device__ int   g_c1;
__device__ int   g_c2;
__device__ float g_gsum[GG * Hh];
__device__ int   g_gcnt[GG];
__device__ float g_m1[GG * Hh];
__device__ float g_m2[GG * Hh];

// ---------------- fp16 split helpers ----------------
__device__ __forceinline__ void split_h2(float a, float b,
                                         unsigned int& hi, unsigned int& lo) {
    __half ha = __float2half_rn(a), hb = __float2half_rn(b);
    float ra = a - __half2float(ha);
    float rb = b - __half2float(hb);
    __half2 h = __halves2half2(ha, hb);
    __half2 l = __halves2half2(__float2half_rn(ra), __float2half_rn(rb));
    hi = *reinterpret_cast<unsigned int*>(&h);
    lo = *reinterpret_cast<unsigned int*>(&l);
}

__device__ __forceinline__ void mma_f16(float4& d,
    unsigned int a0, unsigned int a1, unsigned int a2, unsigned int a3,
    unsigned int b0, unsigned int b1)
{
    asm volatile(
        "mma.sync.aligned.m16n8k16.row.col.f32.f16.f16.f32 "
        "{%0,%1,%2,%3}, {%4,%5,%6,%7}, {%8,%9}, {%0,%1,%2,%3};\n"
        : "+f"(d.x), "+f"(d.y), "+f"(d.z), "+f"(d.w)
        : "r"(a0), "r"(a1), "r"(a2), "r"(a3), "r"(b0), "r"(b1));
}

// ---------------- setup ----------------
__global__ void zero_k() {
    int i = blockIdx.x * blockDim.x + threadIdx.x;
    if (i < Nn)      g_deg[i]  = 0;
    if (i < GG * Hh) g_gsum[i] = 0.f;
    if (i < GG)      g_gcnt[i] = 0;
    if (i < Hh)      { g_colsum[i] = 0.f; g_colsq[i] = 0.f; }
    if (i == 0)      { g_ctr = 0; g_c1 = 0; g_c2 = 0; }
}

// pre-split + pre-pack weights into fp16 hi/lo, k-pair packed layout [kp][256].
// Fused We@W0 rows (kp<64) are recomputed inline (no wprep dependency).
// Block 448 computes g_bias0 = encB @ W0.
__global__ void prep_k(const float* __restrict__ encW, const float* __restrict__ encB,
                       const float* __restrict__ convW) {
    int n = threadIdx.x;
    if (blockIdx.x == KP2TOT) {   // bias block
        float sum = 0.f;
#pragma unroll 8
        for (int j = 0; j < Hh; j++) sum += encB[j] * convW[(size_t)j * Hh + n];
        g_bias0[n] = sum;
        return;
    }
    int kp = blockIdx.x;
    int r0 = kp * 2, r1 = r0 + 1;
    float a, b;
    if (kp < 64) {
        // fused weights: w0f[r][n] = sum_j encW[r][j] * W0[j][n]
        float sa = 0.f, sb = 0.f;
        const float* e0 = encW + (size_t)r0 * Hh;
        const float* e1 = encW + (size_t)r1 * Hh;
#pragma unroll 8
        for (int j = 0; j < Hh; j++) {
            float w = convW[(size_t)j * Hh + n];
            sa += e0[j] * w;
            sb += e1[j] * w;
        }
        a = sa; b = sb;
    } else {
        a = convW[(size_t)(r0 + 128) * Hh + n];
        b = convW[(size_t)(r1 + 128) * Hh + n];
    }
    unsigned int hi, lo;
    split_h2(a, b, hi, lo);
    g_wbh[kp * Hh + n] = hi;
    g_wbl[kp * Hh + n] = lo;
}

__global__ void degree_k(const int* __restrict__ dst, const int* __restrict__ batch) {
    int i = blockIdx.x * blockDim.x + threadIdx.x;
    if (i < Ee) atomicAdd(&g_deg[dst[i]], 1);
    if (i < Nn) atomicAdd(&g_gcnt[batch[i]], 1);
}

// scan (vectorized) + dinv
__global__ void scan_k() {
    __shared__ int wsum[32];
    const int CH = 20;
    int tid = threadIdx.x, lane = tid & 31, wid = tid >> 5;
    int base = tid * CH;
    int dv[CH];
    int s = 0;
    if (base < Nn) {
        const int4* dp = (const int4*)(g_deg + base);
#pragma unroll
        for (int q = 0; q < 5; q++) {
            int4 t = dp[q];
            dv[q * 4 + 0] = t.x; dv[q * 4 + 1] = t.y;
            dv[q * 4 + 2] = t.z; dv[q * 4 + 3] = t.w;
        }
#pragma unroll
        for (int c = 0; c < CH; c++) s += dv[c];
    }
    int inc = s;
#pragma unroll
    for (int o = 1; o < 32; o <<= 1) {
        int t = __shfl_up_sync(0xffffffffu, inc, o);
        if (lane >= o) inc += t;
    }
    if (lane == 31) wsum[wid] = inc;
    __syncthreads();
    if (wid == 0) {
        int v = wsum[lane];
        int iv = v;
#pragma unroll
        for (int o = 1; o < 32; o <<= 1) {
            int t = __shfl_up_sync(0xffffffffu, iv, o);
            if (lane >= o) iv += t;
        }
        wsum[lane] = iv - v;
    }
    __syncthreads();
    int off = wsum[wid] + (inc - s);
    if (base < Nn) {
        int p[CH];
        int run = off;
#pragma unroll
        for (int c = 0; c < CH; c++) { p[c] = run; run += dv[c]; }
        int4*   rp = (int4*)(g_rowptr + base);
        int4*   cp = (int4*)(g_cursor + base);
        float4* fp = (float4*)(g_dinv + base);
#pragma unroll
        for (int q = 0; q < 5; q++) {
            int4 t; t.x = p[q*4]; t.y = p[q*4+1]; t.z = p[q*4+2]; t.w = p[q*4+3];
            rp[q] = t; cp[q] = t;
            float4 f;
            f.x = rsqrtf((float)dv[q*4+0] + 1.f);
            f.y = rsqrtf((float)dv[q*4+1] + 1.f);
            f.z = rsqrtf((float)dv[q*4+2] + 1.f);
            f.w = rsqrtf((float)dv[q*4+3] + 1.f);
            fp[q] = f;
        }
    }
    if (base == Nn) g_rowptr[Nn] = off;
}

__global__ void place_k(const int* __restrict__ src, const int* __restrict__ dst) {
    int i = blockIdx.x * blockDim.x + threadIdx.x;
    if (i >= Ee) return;
    int s = src[i], d = dst[i];
    int pos = atomicAdd(&g_cursor[d], 1);
    g_csrc[pos] = s;
    g_cw[pos]   = g_dinv[s] * g_dinv[d];
}

// ---------------- split-FP16 tensor-core GEMM (R13 structure, BM=128 x BN=64) ----------------
#define BM 128
#define BN 64
#define BK 16
// mode 0: fused first GEMM (A=x, K=128, +g_bias0,  -> g_t)
// mode 2: conv layers 1-3 (A=relu(g_t2*sc+sh), K=256, -> g_t)
__global__ __launch_bounds__(256) void gemm_k(const float* __restrict__ xin,
                                              int mode, int wofs2) {
    __shared__ unsigned int Ah[2][8][BM], Al[2][8][BM];
    __shared__ unsigned int Bh[2][8][BN], Bl[2][8][BN];

    const int K  = (mode == 0) ? XDIM : Hh;
    const int KT = K / BK;
    const float* A = (mode == 0) ? xin : g_t2;

    const int tid  = threadIdx.x;
    const int lane = tid & 31, wid = tid >> 5;
    const int warp_m = wid & 3, warp_n = wid >> 2;
    const int rowBase = blockIdx.y * BM, colBase = blockIdx.x * BN;

    const int arow = tid >> 1;
    const int ak8  = (tid & 1) * 8;
    const int akp  = (tid & 1) * 4;
    const int bkp  = tid >> 5;
    const int bcol = lane * 2;
    const int q = lane >> 2, t = lane & 3, tsw = t << 3;

    const int gr = rowBase + arow;
    const float* aptr = A + (size_t)gr * K + ak8;
    const unsigned int* bhp = g_wbh + wofs2 + (size_t)bkp * Hh + colBase + bcol;
    const unsigned int* blp = g_wbl + wofs2 + (size_t)bkp * Hh + colBase + bcol;
    const int bstep = 8 * Hh;
    const int bcs = bcol ^ ((bkp & 3) << 3);

    float4 acc[2][4];
#pragma unroll
    for (int i = 0; i < 2; i++)
#pragma unroll
        for (int j = 0; j < 4; j++) acc[i][j] = make_float4(0.f, 0.f, 0.f, 0.f);

    float va[8];
    uint2 rbh, rbl;

    // ---- prologue: fetch tile 0 ----
    {
        float4 v0 = make_float4(0.f,0.f,0.f,0.f), v1 = v0;
        if (gr < Nn) { v0 = *(const float4*)aptr; v1 = *(const float4*)(aptr + 4); }
        va[0]=v0.x; va[1]=v0.y; va[2]=v0.z; va[3]=v0.w;
        va[4]=v1.x; va[5]=v1.y; va[6]=v1.z; va[7]=v1.w;
        if (mode == 2) {
            int kk = ak8;
#pragma unroll
            for (int c = 0; c < 8; c++)
                va[c] = fmaxf(va[c] * g_scale[kk + c] + g_shift[kk + c], 0.f);
        }
        rbh = *(const uint2*)bhp;
        rbl = *(const uint2*)blp;
    }
#pragma unroll
    for (int c2 = 0; c2 < 4; c2++) {
        unsigned int hi, lo;
        split_h2(va[2*c2], va[2*c2+1], hi, lo);
        int col = arow ^ (c2 << 3);
        Ah[0][akp + c2][col] = hi;
        Al[0][akp + c2][col] = lo;
    }
    *(uint2*)&Bh[0][bkp][bcs] = rbh;
    *(uint2*)&Bl[0][bkp][bcs] = rbl;
    __syncthreads();

    for (int kt = 0; kt < KT; kt++) {
        const int cur = kt & 1;
        const bool more = (kt + 1 < KT);
        if (more) {
            float4 v0 = make_float4(0.f,0.f,0.f,0.f), v1 = v0;
            if (gr < Nn) {
                const float* ap = aptr + (kt + 1) * BK;
                v0 = *(const float4*)ap; v1 = *(const float4*)(ap + 4);
            }
            va[0]=v0.x; va[1]=v0.y; va[2]=v0.z; va[3]=v0.w;
            va[4]=v1.x; va[5]=v1.y; va[6]=v1.z; va[7]=v1.w;
            if (mode == 2) {
                int kk = (kt + 1) * BK + ak8;
#pragma unroll
                for (int c = 0; c < 8; c++)
                    va[c] = fmaxf(va[c] * g_scale[kk + c] + g_shift[kk + c], 0.f);
            }
            rbh = *(const uint2*)(bhp + (size_t)(kt + 1) * bstep);
            rbl = *(const uint2*)(blp + (size_t)(kt + 1) * bstep);
        }
        // ---- compute on cur buffer ----
        unsigned int bh0[4], bh1[4], bl0[4], bl1[4];
#pragma unroll
        for (int j = 0; j < 4; j++) {
            int nb = (warp_n * 32 + j * 8 + q) ^ tsw;
            bh0[j] = Bh[cur][t][nb];     bh1[j] = Bh[cur][t + 4][nb];
            bl0[j] = Bl[cur][t][nb];     bl1[j] = Bl[cur][t + 4][nb];
        }
#pragma unroll
        for (int i = 0; i < 2; i++) {
            int r  = warp_m * 32 + i * 16 + q;
            int rs  = r ^ tsw;
            int rs8 = (r + 8) ^ tsw;
            unsigned int ah0 = Ah[cur][t][rs],     ah1 = Ah[cur][t][rs8];
            unsigned int ah2 = Ah[cur][t + 4][rs], ah3 = Ah[cur][t + 4][rs8];
            unsigned int al0 = Al[cur][t][rs],     al1 = Al[cur][t][rs8];
            unsigned int al2 = Al[cur][t + 4][rs], al3 = Al[cur][t + 4][rs8];
#pragma unroll
            for (int j = 0; j < 4; j++) {
                mma_f16(acc[i][j], ah0, ah1, ah2, ah3, bh0[j], bh1[j]);
                mma_f16(acc[i][j], ah0, ah1, ah2, ah3, bl0[j], bl1[j]);
                mma_f16(acc[i][j], al0, al1, al2, al3, bh0[j], bh1[j]);
            }
        }
        if (more) {
            const int nxt = cur ^ 1;
#pragma unroll
            for (int c2 = 0; c2 < 4; c2++) {
                unsigned int hi, lo;
                split_h2(va[2*c2], va[2*c2+1], hi, lo);
                int col = arow ^ (c2 << 3);
                Ah[nxt][akp + c2][col] = hi;
                Al[nxt][akp + c2][col] = lo;
            }
            *(uint2*)&Bh[nxt][bkp][bcs] = rbh;
            *(uint2*)&Bl[nxt][bkp][bcs] = rbl;
        }
        __syncthreads();
    }

    // ---- epilogue ----
#pragma unroll
    for (int i = 0; i < 2; i++) {
#pragma unroll
        for (int j = 0; j < 4; j++) {
            int r0 = rowBase + warp_m * 32 + i * 16 + q;
            int c  = colBase + warp_n * 32 + j * 8 + t * 2;
            float bx = 0.f, by = 0.f;
            if (mode == 0) { bx = g_bias0[c]; by = g_bias0[c + 1]; }
            if (r0 < Nn) {
                g_t[(size_t)r0 * Hh + c]     = acc[i][j].x + bx;
                g_t[(size_t)r0 * Hh + c + 1] = acc[i][j].y + by;
            }
            if (r0 + 8 < Nn) {
                g_t[(size_t)(r0 + 8) * Hh + c]     = acc[i][j].z + bx;
                g_t[(size_t)(r0 + 8) * Hh + c + 1] = acc[i][j].w + by;
            }
        }
    }
}

// ---------------- aggregate (warp/node, R13) + fused BN stats + last-block bnprep ----------------
__global__ __launch_bounds__(256) void agg_k(const float* __restrict__ convBi,
                                             const float* __restrict__ gamma,
                                             const float* __restrict__ beta) {
    __shared__ float s_sum[Hh], s_sq[Hh];
    __shared__ int s_last;
    int tid = threadIdx.x, lane = tid & 31;
    s_sum[tid] = 0.f; s_sq[tid] = 0.f;
    __syncthreads();

    int w = blockIdx.x * 8 + (tid >> 5);   // grid = 2500 -> exact
    int beg = g_rowptr[w], end = g_rowptr[w + 1];
    float4 a0 = make_float4(0.f, 0.f, 0.f, 0.f), a1 = a0;
    const float4* T = (const float4*)g_t;
    for (int e = beg; e < end; e++) {
        int   s  = g_csrc[e];
        float wt = g_cw[e];
        float4 v0 = T[s * 64 + lane];
        float4 v1 = T[s * 64 + lane + 32];
        a0.x += v0.x * wt; a0.y += v0.y * wt; a0.z += v0.z * wt; a0.w += v0.w * wt;
        a1.x += v1.x * wt; a1.y += v1.y * wt; a1.z += v1.z * wt; a1.w += v1.w * wt;
    }
    float sn = g_dinv[w]; sn *= sn;
    float4 t0 = T[w * 64 + lane], t1 = T[w * 64 + lane + 32];
    const float4* B4 = (const float4*)convBi;
    float4 b0 = B4[lane], b1 = B4[lane + 32];
    a0.x += t0.x * sn + b0.x; a0.y += t0.y * sn + b0.y;
    a0.z += t0.z * sn + b0.z; a0.w += t0.w * sn + b0.w;
    a1.x += t1.x * sn + b1.x; a1.y += t1.y * sn + b1.y;
    a1.z += t1.z * sn + b1.z; a1.w += t1.w * sn + b1.w;
    ((float4*)g_t2)[w * 64 + lane]      = a0;
    ((float4*)g_t2)[w * 64 + lane + 32] = a1;

    int c0 = lane * 4, c1 = 128 + lane * 4;
    atomicAdd(&s_sum[c0+0], a0.x); atomicAdd(&s_sum[c0+1], a0.y);
    atomicAdd(&s_sum[c0+2], a0.z); atomicAdd(&s_sum[c0+3], a0.w);
    atomicAdd(&s_sum[c1+0], a1.x); atomicAdd(&s_sum[c1+1], a1.y);
    atomicAdd(&s_sum[c1+2], a1.z); atomicAdd(&s_sum[c1+3], a1.w);
    atomicAdd(&s_sq[c0+0], a0.x*a0.x); atomicAdd(&s_sq[c0+1], a0.y*a0.y);
    atomicAdd(&s_sq[c0+2], a0.z*a0.z); atomicAdd(&s_sq[c0+3], a0.w*a0.w);
    atomicAdd(&s_sq[c1+0], a1.x*a1.x); atomicAdd(&s_sq[c1+1], a1.y*a1.y);
    atomicAdd(&s_sq[c1+2], a1.z*a1.z); atomicAdd(&s_sq[c1+3], a1.w*a1.w);
    __syncthreads();
    atomicAdd(&g_colsum[tid], s_sum[tid]);
    atomicAdd(&g_colsq[tid],  s_sq[tid]);

    // ---- last block computes BN scale/shift ----
    __threadfence();
    if (tid == 0) {
        int old = atomicAdd(&g_ctr, 1);
        s_last = (old == gridDim.x - 1);
    }
    __syncthreads();
    if (s_last) {
        __threadfence();
        const float invN = 1.f / (float)Nn;
        float m  = g_colsum[tid] * invN;
        float v  = g_colsq[tid] * invN - m * m;
        float rs = rsqrtf(v + EPSF);
        float sc = gamma[tid] * rs;
        g_scale[tid] = sc;
        g_shift[tid] = beta[tid] - m * sc;
        g_colsum[tid] = 0.f;
        g_colsq[tid]  = 0.f;
        if (tid == 0) g_ctr = 0;
    }
}

// ---------------- global mean pool with fused final BN+ReLU ----------------
__global__ void pool_k(const int* __restrict__ batch) {
    int j  = threadIdx.x;
    float sc = g_scale[j], sh = g_shift[j];
    int r0 = blockIdx.x * 80;
    int cur = -1;
    float acc = 0.f;
    for (int r = 0; r < 80; r++) {
        int n = r0 + r;
        if (n >= Nn) break;
        int b = batch[n];
        if (b != cur) {
            if (cur >= 0) atomicAdd(&g_gsum[cur * Hh + j], acc);
            cur = b; acc = 0.f;
        }
        acc += fmaxf(g_t2[(size_t)n * Hh + j] * sc + sh, 0.f);
    }
    if (cur >= 0) atomicAdd(&g_gsum[cur * Hh + j], acc);
}

// ---------------- fused MLP head: mlp1 -> barrier -> mlp2 -> barrier -> final ----------------
// GG=128 blocks <= 148 SMs -> all co-resident; counter-spin grid barriers are safe.
__global__ __launch_bounds__(256) void head_k(
    const float* __restrict__ fcW1, const float* __restrict__ fcB1,
    const float* __restrict__ fcG1, const float* __restrict__ fcBe1,
    const float* __restrict__ fcW2, const float* __restrict__ fcB2,
    const float* __restrict__ fcG2, const float* __restrict__ fcBe2,
    const float* __restrict__ fcW3, const float* __restrict__ fcB3,
    float* __restrict__ out)
{
    __shared__ float s[Hh];
    int tid = threadIdx.x;
    int g   = blockIdx.x;

    // ---- phase 1: m1 = meanpool @ W1 + b1 ----
    float inv = 1.f / fmaxf((float)g_gcnt[g], 1.f);
    s[tid] = g_gsum[g * Hh + tid] * inv;
    __syncthreads();
    float sum = fcB1[tid];
#pragma unroll 8
    for (int k = 0; k < Hh; k++) sum += s[k] * fcW1[k * Hh + tid];
    g_m1[g * Hh + tid] = sum;

    // ---- grid barrier 1 ----
    __threadfence();
    __syncthreads();
    if (tid == 0) {
        atomicAdd(&g_c1, 1);
        while (atomicAdd(&g_c1, 0) < GG) { }
    }
    __syncthreads();

    // ---- phase 2: BN1+ReLU, m2 = . @ W2 + b2 ----
    float su = 0.f, q = 0.f;
#pragma unroll 8
    for (int r = 0; r < GG; r++) { float v = g_m1[r * Hh + tid]; su += v; q += v * v; }
    float m   = su * (1.f / GG);
    float var = q * (1.f / GG) - m * m;
    float sc  = fcG1[tid] * rsqrtf(var + EPSF);
    float sh  = fcBe1[tid] - m * sc;
    __syncthreads();
    s[tid] = fmaxf(g_m1[g * Hh + tid] * sc + sh, 0.f);
    __syncthreads();
    sum = fcB2[tid];
#pragma unroll 8
    for (int k = 0; k < Hh; k++) sum += s[k] * fcW2[k * Hh + tid];
    g_m2[g * Hh + tid] = sum;

    // ---- grid barrier 2 ----
    __threadfence();
    __syncthreads();
    if (tid == 0) {
        atomicAdd(&g_c2, 1);
        while (atomicAdd(&g_c2, 0) < GG) { }
    }
    __syncthreads();

    // ---- phase 3: BN2, out = . @ W3 + b3 ----
    su = 0.f; q = 0.f;
#pragma unroll 8
    for (int r = 0; r < GG; r++) { float v = g_m2[r * Hh + tid]; su += v; q += v * v; }
    m   = su * (1.f / GG);
    var = q * (1.f / GG) - m * m;
    sc  = fcG2[tid] * rsqrtf(var + EPSF);
    sh  = fcBe2[tid] - m * sc;
    __syncthreads();
    s[tid] = g_m2[g * Hh + tid] * sc + sh;
    __syncthreads();
    if (tid < CC) {
        float o = fcB3[tid];
        for (int k = 0; k < Hh; k++) o += s[k] * fcW3[k * CC + tid];
        out[g * CC + tid] = o;
    }
}

// ---------------- launch ----------------
extern "C" void kernel_launch(void* const* d_in, const int* in_sizes, int n_in,
                              void* d_out, int out_size) {
    const float* x     = (const float*)d_in[0];
    const int*   ei    = (const int*)  d_in[1];
    const int*   batch = (const int*)  d_in[2];
    const float* encW  = (const float*)d_in[3];
    const float* encB  = (const float*)d_in[4];
    const float* convW = (const float*)d_in[5];
    const float* convB = (const float*)d_in[6];
    const float* bnG   = (const float*)d_in[7];
    const float* bnB   = (const float*)d_in[8];
    const float* fcW1  = (const float*)d_in[9];
    const float* fcB1  = (const float*)d_in[10];
    const float* fcG1  = (const float*)d_in[11];
    const float* fcBe1 = (const float*)d_in[12];
    const float* fcW2  = (const float*)d_in[13];
    const float* fcB2  = (const float*)d_in[14];
    const float* fcG2  = (const float*)d_in[15];
    const float* fcBe2 = (const float*)d_in[16];
    const float* fcW3  = (const float*)d_in[17];
    const float* fcB3  = (const float*)d_in[18];
    const int* srcp = ei;
    const int* dstp = ei + Ee;
    float* out = (float*)d_out;

    dim3 gg(Hh / BN, (Nn + BM - 1) / BM);   // (4, 157)

    zero_k<<<(GG * Hh + 255) / 256, 256>>>();
    prep_k<<<KP2TOT + 1, 256>>>(encW, encB, convW);
    gemm_k<<<gg, 256>>>(x, 0, 0);                 // fused enc+conv0 [capture]

    degree_k<<<(Ee + 255) / 256, 256>>>(dstp, batch);
    scan_k  <<<1, 1024>>>();
    place_k <<<(Ee + 255) / 256, 256>>>(srcp, dstp);

    agg_k<<<Nn / 8, 256>>>(convB, bnG, bnB);
    for (int l = 1; l < LL; l++) {
        gemm_k<<<gg, 256>>>(nullptr, 2, (64 + (l - 1) * 128) * Hh);
        agg_k <<<Nn / 8, 256>>>(convB + l * Hh, bnG + l * Hh, bnB + l * Hh);
    }

    pool_k<<<250, 256>>>(batch);
    head_k<<<GG, 256>>>(fcW1, fcB1, fcG1, fcBe1, fcW2, fcB2,
                        fcG2, fcBe2, fcW3, fcB3, out);
}